// round 14
// baseline (speedup 1.0000x reference)
#include <cuda_runtime.h>

#define SQ   1024   // spatial sequence length (16*64)
#define CH   64     // channels == heads (c = 1 per head)
#define NHB  128    // batch * heads
#define M    16     // Chebyshev terms
#define RAD  8.0f   // fixed Chebyshev interval [-RAD, RAD] for q
#define KS   0.18033688011112042f   // log2(e) / sqrt(64)
#define PI_M 0.19634954084936207f   // pi / 16

// ONLY inter-kernel state: 32 Chebyshev coefficients per head (16KB).
__device__ float g_coef[NHB * 32];

typedef unsigned long long u64t;

__device__ __forceinline__ float ex2f(float x) {
    float r;
    asm("ex2.approx.ftz.f32 %0, %1;" : "=f"(r) : "f"(x));
    return r;
}
__device__ __forceinline__ u64t pack2(float lo, float hi) {
    u64t r;
    asm("mov.b64 %0, {%1, %2};" : "=l"(r) : "f"(lo), "f"(hi));
    return r;
}
__device__ __forceinline__ u64t fma2(u64t a, u64t b, u64t c) {
    u64t d;
    asm("fma.rn.f32x2 %0, %1, %2, %3;" : "=l"(d) : "l"(a), "l"(b), "l"(c));
    return d;
}

// ---------------------------------------------------------------------------
// K1: per-head Chebyshev coefficients, straight from x.
// Block = head (128 blocks -> every SM busy), 512 threads (16 warps).
//   Phase 1: k-hat, v row GEMV (thread = 2 consecutive t, 64 coalesced
//            float2 LDGs, x is L2-resident). k-hat/v live only in smem.
//   Phase 2: warp w evaluates Chebyshev node w (32 ex2+fma per lane).
//   Phase 3: DCT -> 32 coefficients -> g_coef.
// ---------------------------------------------------------------------------
__global__ __launch_bounds__(512) void coef_kernel(
    const float* __restrict__ x,
    const float* __restrict__ Wk, const float* __restrict__ bk,
    const float* __restrict__ Wv, const float* __restrict__ bv)
{
    __shared__ __align__(16) float wk_s[CH], wv_s[CH];
    __shared__ __align__(16) float kh[SQ], vs[SQ];
    __shared__ float fj[M], gj[M];

    const int tid = threadIdx.x;
    const int hb  = blockIdx.x;
    const int b   = hb >> 6;
    const int h   = hb & 63;

    if (tid < CH)            wk_s[tid]      = Wk[h * CH + tid] * KS;
    else if (tid < 2 * CH)   wv_s[tid - CH] = Wv[h * CH + (tid - CH)];
    __syncthreads();

    // Phase 1: GEMV for 2 consecutive t per thread.
    const int t0 = tid * 2;
    const float bkh = bk[h] * KS, bvh = bv[h];
    u64t kk = pack2(bkh, bkh);
    u64t vv = pack2(bvh, bvh);
    const float* xb = x + (size_t)b * CH * SQ + t0;
#pragma unroll
    for (int c = 0; c < CH; c++) {
        float2 xv = *reinterpret_cast<const float2*>(xb + c * SQ);
        u64t x2 = pack2(xv.x, xv.y);
        float wkc = wk_s[c], wvc = wv_s[c];
        kk = fma2(pack2(wkc, wkc), x2, kk);
        vv = fma2(pack2(wvc, wvc), x2, vv);
    }
    *reinterpret_cast<u64t*>(&kh[t0]) = kk;
    *reinterpret_cast<u64t*>(&vs[t0]) = vv;
    __syncthreads();

    // Phase 2: warp w -> node w.
    const int w = tid >> 5, l = tid & 31;
    const float xw = RAD * cosf(((float)w + 0.5f) * PI_M);
    float f0 = 0.f, g0 = 0.f;
#pragma unroll 8
    for (int t = l; t < SQ; t += 32) {
        float e = ex2f(xw * kh[t]);
        f0 += e;
        g0 = fmaf(e, vs[t], g0);
    }
#pragma unroll
    for (int d = 16; d; d >>= 1) {
        f0 += __shfl_xor_sync(0xffffffffu, f0, d);
        g0 += __shfl_xor_sync(0xffffffffu, g0, d);
    }
    if (l == 0) { fj[w] = f0; gj[w] = g0; }
    __syncthreads();

    // Phase 3: DCT -> coefficients.
    if (tid < M) {
        float af = 0.f, ag = 0.f;
#pragma unroll
        for (int j = 0; j < M; j++) {
            float wgt = cosf((float)tid * ((float)j + 0.5f) * PI_M);
            af = fmaf(fj[j], wgt, af);
            ag = fmaf(gj[j], wgt, ag);
        }
        const float sc = (tid == 0) ? (1.0f / M) : (2.0f / M);
        g_coef[hb * 32 + tid]      = af * sc;
        g_coef[hb * 32 + 16 + tid] = ag * sc;
    }
}

// ---------------------------------------------------------------------------
// K2: q projection + Clenshaw + Wo GEMM + residual.
// Block = (8-s tile, b) -> 256 blocks (2/SM), 512 threads -> 32 warps/SM.
// Thread (o = tid>>3, si = tid&7) handles one (head/out-channel, s) pair.
// Residual comes from the staged x tile in smem (no extra LDG).
// ---------------------------------------------------------------------------
__global__ __launch_bounds__(512) void qout_kernel(
    const float* __restrict__ x,
    const float* __restrict__ Wq, const float* __restrict__ bq,
    const float* __restrict__ Wo, const float* __restrict__ bo,
    float* __restrict__ outp)
{
    __shared__ __align__(16) float wq[CH][68];   // 272B rows, 16B-divisible
    __shared__ __align__(16) float wo[CH][68];
    __shared__ __align__(16) float xt[CH][12];   // 8-s tile, 48B rows
    __shared__ float ot[CH][9];                  // o tile (scalar access)
    __shared__ float ca[CH][17], cb[CH][17];

    const int tid = threadIdx.x;
    const int b   = blockIdx.y;
    const int s0  = blockIdx.x * 8;

    // ---- upfront staging: all LDGs independent, fully coalesced ----
    {
        const int i = tid * 8;                    // 512*8 = 4096 = CH*CH
        float4 a0 = *reinterpret_cast<const float4*>(Wq + i);
        float4 a1 = *reinterpret_cast<const float4*>(Wq + i + 4);
        float4 b0 = *reinterpret_cast<const float4*>(Wo + i);
        float4 b1 = *reinterpret_cast<const float4*>(Wo + i + 4);
        const int r = i >> 6, c0 = i & 63;
        *reinterpret_cast<float4*>(&wq[r][c0])     = a0;
        *reinterpret_cast<float4*>(&wq[r][c0 + 4]) = a1;
        *reinterpret_cast<float4*>(&wo[r][c0])     = b0;
        *reinterpret_cast<float4*>(&wo[r][c0 + 4]) = b1;
    }
    {
        const int i = tid * 4;                    // 512*4 = 2048 = CH*32
        float4 cv = *reinterpret_cast<const float4*>(g_coef + b * CH * 32 + i);
#pragma unroll
        for (int u = 0; u < 4; u++) {
            const int idx = i + u, h = idx >> 5, r = idx & 31;
            const float val = (&cv.x)[u];
            if (r < 16) ca[h][r] = val; else cb[h][r - 16] = val;
        }
    }
    if (tid < 128) {                              // x tile: 64 rows x 2 float4
        const int c = tid >> 1, j = tid & 1;
        float4 xv = *reinterpret_cast<const float4*>(
            x + (size_t)(b * CH + c) * SQ + s0 + 4 * j);
        *reinterpret_cast<float4*>(&xt[c][4 * j]) = xv;
    }
    __syncthreads();

    const int o  = tid >> 3;
    const int si = tid & 7;

    // ---- q GEMV: two split scalar chains ----
    float acc0 = bq[o], acc1 = 0.f;
#pragma unroll
    for (int c8 = 0; c8 < 8; c8++) {
        float4 wA = *reinterpret_cast<const float4*>(&wq[o][c8 * 8]);
        float4 wB = *reinterpret_cast<const float4*>(&wq[o][c8 * 8 + 4]);
        const int cb_ = c8 * 8;
        acc0 = fmaf(wA.x, xt[cb_ + 0][si], acc0);
        acc0 = fmaf(wA.y, xt[cb_ + 1][si], acc0);
        acc0 = fmaf(wA.z, xt[cb_ + 2][si], acc0);
        acc0 = fmaf(wA.w, xt[cb_ + 3][si], acc0);
        acc1 = fmaf(wB.x, xt[cb_ + 4][si], acc1);
        acc1 = fmaf(wB.y, xt[cb_ + 5][si], acc1);
        acc1 = fmaf(wB.z, xt[cb_ + 6][si], acc1);
        acc1 = fmaf(wB.w, xt[cb_ + 7][si], acc1);
    }
    const float q = acc0 + acc1;
    const float res = xt[o][si];                  // residual from staged tile

    // ---- Clenshaw (fixed interval: u = q / RAD) ----
    {
        const float u  = q * (1.0f / RAD);
        const float t2 = 2.f * u;
        float b1 = 0.f, b2 = 0.f, d1 = 0.f, d2 = 0.f;
#pragma unroll
        for (int k = M - 1; k >= 1; k--) {
            float cak = ca[o][k], cbk = cb[o][k];
            float nb = fmaf(t2, b1, cak - b2); b2 = b1; b1 = nb;
            float nd = fmaf(t2, d1, cbk - d2); d2 = d1; d1 = nd;
        }
        float f = fmaf(u, b1, ca[o][0] - b2);
        float g = fmaf(u, d1, cb[o][0] - d2);
        ot[o][si] = __fdividef(g, f);
    }
    __syncthreads();

    // ---- Wo GEMM + residual ----
    float a0 = bo[o], a1 = 0.f;
#pragma unroll
    for (int c8 = 0; c8 < 8; c8++) {
        float4 wA = *reinterpret_cast<const float4*>(&wo[o][c8 * 8]);
        float4 wB = *reinterpret_cast<const float4*>(&wo[o][c8 * 8 + 4]);
        const int cb_ = c8 * 8;
        a0 = fmaf(wA.x, ot[cb_ + 0][si], a0);
        a0 = fmaf(wA.y, ot[cb_ + 1][si], a0);
        a0 = fmaf(wA.z, ot[cb_ + 2][si], a0);
        a0 = fmaf(wA.w, ot[cb_ + 3][si], a0);
        a1 = fmaf(wB.x, ot[cb_ + 4][si], a1);
        a1 = fmaf(wB.y, ot[cb_ + 5][si], a1);
        a1 = fmaf(wB.z, ot[cb_ + 6][si], a1);
        a1 = fmaf(wB.w, ot[cb_ + 7][si], a1);
    }
    outp[(size_t)(b * CH + o) * SQ + s0 + si] = a0 + a1 + res;
}

extern "C" void kernel_launch(void* const* d_in, const int* in_sizes, int n_in,
                              void* d_out, int out_size)
{
    const float* x  = (const float*)d_in[0];
    const float* Wq = (const float*)d_in[1];
    const float* bq = (const float*)d_in[2];
    const float* Wk = (const float*)d_in[3];
    const float* bk = (const float*)d_in[4];
    const float* Wv = (const float*)d_in[5];
    const float* bv = (const float*)d_in[6];
    const float* Wo = (const float*)d_in[7];
    const float* bo = (const float*)d_in[8];
    float* out = (float*)d_out;

    coef_kernel<<<NHB, 512>>>(x, Wk, bk, Wv, bv);

    dim3 grid(SQ / 8, 2);
    qout_kernel<<<grid, 512>>>(x, Wq, bq, Wo, bo, out);
}

// round 16
// speedup vs baseline: 1.0625x; 1.0625x over previous
#include <cuda_runtime.h>

#define SQ   1024   // spatial sequence length (16*64)
#define CH   64     // channels == heads (c = 1 per head)
#define NHB  128    // batch * heads
#define M    16     // Chebyshev terms
#define RAD  8.0f   // fixed Chebyshev interval [-RAD, RAD] for q
#define KS   0.18033688011112042f   // log2(e) / sqrt(64)
#define PI_M 0.19634954084936207f   // pi / 16

// Inter-kernel state: per-head attention outputs (512KB).
__device__ float g_o[NHB * SQ];

typedef unsigned long long u64t;

__device__ __forceinline__ float ex2f(float x) {
    float r;
    asm("ex2.approx.ftz.f32 %0, %1;" : "=f"(r) : "f"(x));
    return r;
}
__device__ __forceinline__ u64t pack2(float lo, float hi) {
    u64t r;
    asm("mov.b64 %0, {%1, %2};" : "=l"(r) : "f"(lo), "f"(hi));
    return r;
}
__device__ __forceinline__ float2 unpack2(u64t v) {
    float2 f;
    asm("mov.b64 {%0, %1}, %2;" : "=f"(f.x), "=f"(f.y) : "l"(v));
    return f;
}
__device__ __forceinline__ u64t fma2(u64t a, u64t b, u64t c) {
    u64t d;
    asm("fma.rn.f32x2 %0, %1, %2, %3;" : "=l"(d) : "l"(a), "l"(b), "l"(c));
    return d;
}

// ---------------------------------------------------------------------------
// K1: everything per head in one block: QKV projection rows (single shared
// x pass, packed f32x2), 16 Chebyshev node sums (warp w <-> node w), DCT,
// Clenshaw on in-register q -> g_o. Block = head (128, full chip), 512 thr.
// ---------------------------------------------------------------------------
__global__ __launch_bounds__(512) void fused_head(
    const float* __restrict__ x,
    const float* __restrict__ Wq, const float* __restrict__ bq,
    const float* __restrict__ Wk, const float* __restrict__ bk,
    const float* __restrict__ Wv, const float* __restrict__ bv)
{
    __shared__ __align__(16) float wqs[CH], wks[CH], wvs[CH];
    __shared__ __align__(16) float kh[SQ], vs[SQ];
    __shared__ float fj[M], gj[M], ca[M], cb[M];

    const int tid = threadIdx.x;
    const int hb  = blockIdx.x;
    const int b   = hb >> 6;
    const int h   = hb & 63;

    if (tid < CH)            wqs[tid]          = Wq[h * CH + tid];
    else if (tid < 2 * CH)   wks[tid - CH]     = Wk[h * CH + (tid - CH)] * KS;
    else if (tid < 3 * CH)   wvs[tid - 2 * CH] = Wv[h * CH + (tid - 2 * CH)];
    const float bqh = bq[h], bkh = bk[h] * KS, bvh = bv[h];
    __syncthreads();

    // ---- QKV GEMV: thread = 2 consecutive t; one x pass, 3 fma2 each ----
    const int t0 = tid * 2;
    u64t q2 = pack2(bqh, bqh);
    u64t k2 = pack2(bkh, bkh);
    u64t v2 = pack2(bvh, bvh);
    const float* xb = x + (size_t)b * CH * SQ + t0;
#pragma unroll
    for (int c = 0; c < CH; c++) {
        float2 xv = *reinterpret_cast<const float2*>(xb + c * SQ);
        u64t x2 = pack2(xv.x, xv.y);
        float wv_ = wvs[c], wk_ = wks[c], wq_ = wqs[c];
        q2 = fma2(pack2(wq_, wq_), x2, q2);
        k2 = fma2(pack2(wk_, wk_), x2, k2);
        v2 = fma2(pack2(wv_, wv_), x2, v2);
    }
    *reinterpret_cast<u64t*>(&kh[t0]) = k2;
    *reinterpret_cast<u64t*>(&vs[t0]) = v2;
    __syncthreads();

    // ---- node sums: warp w evaluates node w (16 warps, 16 nodes) ----
    const int w = tid >> 5, l = tid & 31;
    {
        const float xw = RAD * cosf(((float)w + 0.5f) * PI_M);
        float f0 = 0.f, g0 = 0.f;
#pragma unroll 8
        for (int t = l; t < SQ; t += 32) {
            float e = ex2f(xw * kh[t]);
            f0 += e;
            g0 = fmaf(e, vs[t], g0);
        }
#pragma unroll
        for (int d = 16; d; d >>= 1) {
            f0 += __shfl_xor_sync(0xffffffffu, f0, d);
            g0 += __shfl_xor_sync(0xffffffffu, g0, d);
        }
        if (l == 0) { fj[w] = f0; gj[w] = g0; }
    }
    __syncthreads();

    // ---- DCT -> Chebyshev coefficients ----
    if (tid < M) {
        float af = 0.f, ag = 0.f;
#pragma unroll
        for (int j = 0; j < M; j++) {
            float wgt = cosf((float)tid * ((float)j + 0.5f) * PI_M);
            af = fmaf(fj[j], wgt, af);
            ag = fmaf(gj[j], wgt, ag);
        }
        const float sc = (tid == 0) ? (1.0f / M) : (2.0f / M);
        ca[tid] = af * sc;
        cb[tid] = ag * sc;
    }
    __syncthreads();

    // ---- Clenshaw on in-register q (2 values) -> g_o ----
    {
        float2 qq = unpack2(q2);
        const float IR = 1.0f / RAD;
        float u0 = qq.x * IR, u1 = qq.y * IR;
        float t20 = 2.f * u0, t21 = 2.f * u1;
        float b10 = 0.f, b20 = 0.f, d10 = 0.f, d20 = 0.f;
        float b11 = 0.f, b21 = 0.f, d11 = 0.f, d21 = 0.f;
#pragma unroll
        for (int k = M - 1; k >= 1; k--) {
            float cak = ca[k], cbk = cb[k];
            float nb0 = fmaf(t20, b10, cak - b20); b20 = b10; b10 = nb0;
            float nd0 = fmaf(t20, d10, cbk - d20); d20 = d10; d10 = nd0;
            float nb1 = fmaf(t21, b11, cak - b21); b21 = b11; b11 = nb1;
            float nd1 = fmaf(t21, d11, cbk - d21); d21 = d11; d11 = nd1;
        }
        float f0 = fmaf(u0, b10, ca[0] - b20);
        float g0 = fmaf(u0, d10, cb[0] - d20);
        float f1 = fmaf(u1, b11, ca[0] - b21);
        float g1 = fmaf(u1, d11, cb[0] - d21);
        float2 o2;
        o2.x = __fdividef(g0, f0);
        o2.y = __fdividef(g1, f1);
        *reinterpret_cast<float2*>(g_o + (size_t)hb * SQ + t0) = o2;
    }
}

// ---------------------------------------------------------------------------
// K2: output projection + residual. Block = (8-s tile, b) -> 256 blocks,
// 256 threads. Thread (o = tid>>2, sp = tid&3) -> 2 s values (all-vector
// smem accesses: float4 weights, float2 operands, packed fma2).
// ---------------------------------------------------------------------------
__global__ __launch_bounds__(256) void out_proj(
    const float* __restrict__ x,
    const float* __restrict__ Wo, const float* __restrict__ bo,
    float* __restrict__ outp)
{
    __shared__ __align__(16) float wo[CH][68];   // 272B rows (16B-divisible)
    __shared__ __align__(16) float ot[CH][12];   // 48B rows (16B-divisible)

    const int tid = threadIdx.x;
    const int b   = blockIdx.y;
    const int s0  = blockIdx.x * 8;
    const int o   = tid >> 2;
    const int sp  = tid & 3;

    // residual + bias hoisted before the barrier (independent LDGs)
    const size_t oidx = (size_t)(b * CH + o) * SQ + s0 + 2 * sp;
    const float2 res = *reinterpret_cast<const float2*>(x + oidx);
    const float bos = bo[o];

    // stage Wo: 16 floats per thread, coalesced float4
    {
        const int i = tid * 16;
        const int r = i >> 6, c0 = i & 63;
#pragma unroll
        for (int u = 0; u < 4; u++) {
            float4 wv = *reinterpret_cast<const float4*>(Wo + i + 4 * u);
            *reinterpret_cast<float4*>(&wo[r][c0 + 4 * u]) = wv;
        }
    }
    // stage o tile: 64 rows x 8 s, one float2 per thread, coalesced
    {
        const int c = tid >> 2, j = tid & 3;
        float2 ov = *reinterpret_cast<const float2*>(
            g_o + (size_t)(b * CH + c) * SQ + s0 + 2 * j);
        ot[c][2 * j]     = ov.x;
        ot[c][2 * j + 1] = ov.y;
    }
    __syncthreads();

    // GEMV in packed f32x2
    u64t acc = pack2(bos, bos);
#pragma unroll
    for (int c8 = 0; c8 < CH / 8; c8++) {
        float4 wA = *reinterpret_cast<const float4*>(&wo[o][c8 * 8]);
        float4 wB = *reinterpret_cast<const float4*>(&wo[o][c8 * 8 + 4]);
#pragma unroll
        for (int u = 0; u < 4; u++) {
            u64t xa = *reinterpret_cast<const u64t*>(&ot[c8 * 8 + u][2 * sp]);
            acc = fma2(pack2((&wA.x)[u], (&wA.x)[u]), xa, acc);
        }
#pragma unroll
        for (int u = 0; u < 4; u++) {
            u64t xb2 = *reinterpret_cast<const u64t*>(&ot[c8 * 8 + 4 + u][2 * sp]);
            acc = fma2(pack2((&wB.x)[u], (&wB.x)[u]), xb2, acc);
        }
    }
    float2 a = unpack2(acc);
    float2 o2;
    o2.x = a.x + res.x;
    o2.y = a.y + res.y;
    *reinterpret_cast<float2*>(outp + oidx) = o2;
}

extern "C" void kernel_launch(void* const* d_in, const int* in_sizes, int n_in,
                              void* d_out, int out_size)
{
    const float* x  = (const float*)d_in[0];
    const float* Wq = (const float*)d_in[1];
    const float* bq = (const float*)d_in[2];
    const float* Wk = (const float*)d_in[3];
    const float* bk = (const float*)d_in[4];
    const float* Wv = (const float*)d_in[5];
    const float* bv = (const float*)d_in[6];
    const float* Wo = (const float*)d_in[7];
    const float* bo = (const float*)d_in[8];
    float* out = (float*)d_out;

    fused_head<<<NHB, 512>>>(x, Wq, bq, Wk, bk, Wv, bv);

    dim3 grid(SQ / 8, 2);
    out_proj<<<grid, 256>>>(x, Wo, bo, out);
}